// round 1
// baseline (speedup 1.0000x reference)
#include <cuda_runtime.h>
#include <cuda_bf16.h>

#define BB 8
#define LL 200
#define HH 128
#define NHH 4
#define DHH 32
// scale = 1/sqrt(32)
#define SCALE 0.17677669529663688f

// Scratch: projected Q (pre-scaled), K+posK, V+posV
__device__ float g_Q[BB * LL * HH];
__device__ float g_K[BB * LL * HH];
__device__ float g_V[BB * LL * HH];

// ---------------------------------------------------------------------------
// Projection kernel: 16 rows per CTA, 128 threads (one output column each).
// Q = q @ Qw^T + Qb          (then scaled by 1/sqrt(DH))
// K = k @ Kw^T + Kb + absposK
// V = k @ Vw^T + Vb + absposV
// ---------------------------------------------------------------------------
__global__ __launch_bounds__(128) void proj_kernel(
    const float* __restrict__ queries, const float* __restrict__ keys,
    const float* __restrict__ apK, const float* __restrict__ apV,
    const float* __restrict__ Qw, const float* __restrict__ Qb,
    const float* __restrict__ Kw, const float* __restrict__ Kb,
    const float* __restrict__ Vw, const float* __restrict__ Vb)
{
    __shared__ float4 xq[16 * 32];
    __shared__ float4 xk[16 * 32];
    const int tid  = threadIdx.x;      // 0..127
    const int row0 = blockIdx.x * 16;  // 100 CTAs * 16 = 1600 rows

    const float4* q4 = reinterpret_cast<const float4*>(queries) + row0 * 32;
    const float4* k4 = reinterpret_cast<const float4*>(keys)    + row0 * 32;
    for (int i = tid; i < 16 * 32; i += 128) { xq[i] = q4[i]; xk[i] = k4[i]; }
    __syncthreads();

    const int col = tid;
    float acc[16];

    // ---- Q projection ----
    {
        const float4* W4 = reinterpret_cast<const float4*>(Qw) + col * 32;
        const float b = Qb[col];
        #pragma unroll
        for (int r = 0; r < 16; r++) acc[r] = b;
        #pragma unroll 8
        for (int j = 0; j < 32; j++) {
            const float4 w = W4[j];
            #pragma unroll
            for (int r = 0; r < 16; r++) {
                const float4 x = xq[r * 32 + j];
                acc[r] += w.x * x.x + w.y * x.y + w.z * x.z + w.w * x.w;
            }
        }
        #pragma unroll
        for (int r = 0; r < 16; r++)
            g_Q[(row0 + r) * HH + col] = acc[r] * SCALE;
    }
    // ---- K projection (+ abs pos K) ----
    {
        const float4* W4 = reinterpret_cast<const float4*>(Kw) + col * 32;
        const float b = Kb[col];
        #pragma unroll
        for (int r = 0; r < 16; r++) acc[r] = b;
        #pragma unroll 8
        for (int j = 0; j < 32; j++) {
            const float4 w = W4[j];
            #pragma unroll
            for (int r = 0; r < 16; r++) {
                const float4 x = xk[r * 32 + j];
                acc[r] += w.x * x.x + w.y * x.y + w.z * x.z + w.w * x.w;
            }
        }
        #pragma unroll
        for (int r = 0; r < 16; r++)
            g_K[(row0 + r) * HH + col] = acc[r] + apK[(row0 + r) * HH + col];
    }
    // ---- V projection (+ abs pos V) ----
    {
        const float4* W4 = reinterpret_cast<const float4*>(Vw) + col * 32;
        const float b = Vb[col];
        #pragma unroll
        for (int r = 0; r < 16; r++) acc[r] = b;
        #pragma unroll 8
        for (int j = 0; j < 32; j++) {
            const float4 w = W4[j];
            #pragma unroll
            for (int r = 0; r < 16; r++) {
                const float4 x = xk[r * 32 + j];
                acc[r] += w.x * x.x + w.y * x.y + w.z * x.z + w.w * x.w;
            }
        }
        #pragma unroll
        for (int r = 0; r < 16; r++)
            g_V[(row0 + r) * HH + col] = acc[r] + apV[(row0 + r) * HH + col];
    }
}

// ---------------------------------------------------------------------------
// Attention kernel: one CTA per (b, l). 256 threads = 8 warps.
// Phase A: logits[h][m] = Qscaled . (K[m] + tK[l,m])  for m <= l
// Phase B: per-head softmax (or uniform 1/L for time-masked query rows)
// Phase C: out = sum_m p[h][m] * (V[m] + tV[l,m])
// ---------------------------------------------------------------------------
__global__ __launch_bounds__(256) void attn_kernel(
    const float* __restrict__ tK, const float* __restrict__ tV,
    const int*   __restrict__ tmask, float* __restrict__ out)
{
    const int l = blockIdx.x;
    const int b = blockIdx.y;
    const int tid  = threadIdx.x;
    const int w    = tid >> 5;
    const int lane = tid & 31;

    __shared__ float4 sQ[32];
    __shared__ float  sP[NHH * LL];
    __shared__ float4 sRed[8 * 32];

    const bool masked = (tmask[b * LL + l] != 0);

    if (tid < 32)
        sQ[tid] = reinterpret_cast<const float4*>(g_Q)[(b * LL + l) * 32 + tid];
    __syncthreads();

    // ---------------- Phase A: logits ----------------
    if (!masked) {
        const float4* tK4 = reinterpret_cast<const float4*>(tK) + (size_t)(b * LL + l) * LL * 32;
        const float4* K4  = reinterpret_cast<const float4*>(g_K) + (size_t)b * LL * 32;
        const float4 q = sQ[lane];
        const int head = lane >> 3;
        #pragma unroll 2
        for (int m = w; m <= l; m += 8) {
            const float4 t = tK4[m * 32 + lane];
            const float4 k = K4[m * 32 + lane];
            float s = q.x * (t.x + k.x) + q.y * (t.y + k.y)
                    + q.z * (t.z + k.z) + q.w * (t.w + k.w);
            s += __shfl_down_sync(0xffffffffu, s, 4);
            s += __shfl_down_sync(0xffffffffu, s, 2);
            s += __shfl_down_sync(0xffffffffu, s, 1);
            if ((lane & 7) == 0) sP[head * LL + m] = s;
        }
    }
    __syncthreads();

    // ---------------- Phase B: softmax ----------------
    if (masked) {
        const float invL = 1.0f / (float)LL;
        for (int i = tid; i < NHH * LL; i += 256) sP[i] = invL;
    } else if (w < NHH) {
        const int h = w;
        float mx = -3.4e38f;
        for (int m = lane; m <= l; m += 32) mx = fmaxf(mx, sP[h * LL + m]);
        #pragma unroll
        for (int off = 16; off; off >>= 1)
            mx = fmaxf(mx, __shfl_xor_sync(0xffffffffu, mx, off));
        float sum = 0.0f;
        for (int m = lane; m <= l; m += 32) {
            const float e = __expf(sP[h * LL + m] - mx);
            sP[h * LL + m] = e;
            sum += e;
        }
        #pragma unroll
        for (int off = 16; off; off >>= 1)
            sum += __shfl_xor_sync(0xffffffffu, sum, off);
        const float inv = 1.0f / sum;
        for (int m = lane; m <= l; m += 32) sP[h * LL + m] *= inv;
    }
    __syncthreads();

    // ---------------- Phase C: output ----------------
    {
        const int mEnd = masked ? (LL - 1) : l;
        const float4* tV4 = reinterpret_cast<const float4*>(tV) + (size_t)(b * LL + l) * LL * 32;
        const float4* V4  = reinterpret_cast<const float4*>(g_V) + (size_t)b * LL * 32;
        const int head = lane >> 3;
        float4 acc = make_float4(0.f, 0.f, 0.f, 0.f);
        #pragma unroll 2
        for (int m = w; m <= mEnd; m += 8) {
            const float  p = sP[head * LL + m];
            const float4 t = tV4[m * 32 + lane];
            const float4 v = V4[m * 32 + lane];
            acc.x += p * (t.x + v.x);
            acc.y += p * (t.y + v.y);
            acc.z += p * (t.z + v.z);
            acc.w += p * (t.w + v.w);
        }
        sRed[w * 32 + lane] = acc;
    }
    __syncthreads();

    if (tid < 32) {
        float4 r = sRed[tid];
        #pragma unroll
        for (int w2 = 1; w2 < 8; w2++) {
            const float4 a = sRed[w2 * 32 + tid];
            r.x += a.x; r.y += a.y; r.z += a.z; r.w += a.w;
        }
        reinterpret_cast<float4*>(out)[(b * LL + l) * 32 + tid] = r;
    }
}

extern "C" void kernel_launch(void* const* d_in, const int* in_sizes, int n_in,
                              void* d_out, int out_size)
{
    const float* queries = (const float*)d_in[0];
    const float* keys    = (const float*)d_in[1];
    const int*   tmask   = (const int*)  d_in[2];
    // d_in[3] = attn_mask (causal triu, computed analytically -> unused)
    const float* tK      = (const float*)d_in[4];
    const float* tV      = (const float*)d_in[5];
    const float* apK     = (const float*)d_in[6];
    const float* apV     = (const float*)d_in[7];
    const float* Qw      = (const float*)d_in[8];
    const float* Qb      = (const float*)d_in[9];
    const float* Kw      = (const float*)d_in[10];
    const float* Kb      = (const float*)d_in[11];
    const float* Vw      = (const float*)d_in[12];
    const float* Vb      = (const float*)d_in[13];
    float* out = (float*)d_out;

    proj_kernel<<<100, 128>>>(queries, keys, apK, apV, Qw, Qb, Kw, Kb, Vw, Vb);
    dim3 grid(LL, BB);
    attn_kernel<<<grid, 256>>>(tK, tV, tmask, out);
}

// round 2
// speedup vs baseline: 1.1925x; 1.1925x over previous
#include <cuda_runtime.h>
#include <cuda_bf16.h>

#define BB 8
#define LL 200
#define HH 128
#define NHH 4
#define DHH 32
#define SCALE 0.17677669529663688f   // 1/sqrt(32)

__device__ float g_Q[BB * LL * HH];
__device__ float g_K[BB * LL * HH];
__device__ float g_V[BB * LL * HH];

// ---------------------------------------------------------------------------
// Projection: 200 CTAs x 8 rows, 128 threads (one output column each).
// Q = q @ Qw^T + Qb  (pre-scaled);  K = k @ Kw^T + Kb + apK;  V = k @ Vw^T + Vb + apV
// ---------------------------------------------------------------------------
__global__ __launch_bounds__(128) void proj_kernel(
    const float* __restrict__ queries, const float* __restrict__ keys,
    const float* __restrict__ apK, const float* __restrict__ apV,
    const float* __restrict__ Qw, const float* __restrict__ Qb,
    const float* __restrict__ Kw, const float* __restrict__ Kb,
    const float* __restrict__ Vw, const float* __restrict__ Vb)
{
    __shared__ float4 xq[8 * 32];
    __shared__ float4 xk[8 * 32];
    const int tid  = threadIdx.x;
    const int row0 = blockIdx.x * 8;   // 200 CTAs * 8 = 1600 rows

    const float4* q4 = reinterpret_cast<const float4*>(queries) + row0 * 32;
    const float4* k4 = reinterpret_cast<const float4*>(keys)    + row0 * 32;
    for (int i = tid; i < 8 * 32; i += 128) { xq[i] = q4[i]; xk[i] = k4[i]; }
    __syncthreads();

    const int col = tid;
    float acc[8];

    // ---- Q ----
    {
        const float4* W4 = reinterpret_cast<const float4*>(Qw) + col * 32;
        const float b = Qb[col];
        #pragma unroll
        for (int r = 0; r < 8; r++) acc[r] = b;
        #pragma unroll 8
        for (int j = 0; j < 32; j++) {
            const float4 w = W4[j];
            #pragma unroll
            for (int r = 0; r < 8; r++) {
                const float4 x = xq[r * 32 + j];
                acc[r] += w.x * x.x + w.y * x.y + w.z * x.z + w.w * x.w;
            }
        }
        #pragma unroll
        for (int r = 0; r < 8; r++)
            g_Q[(row0 + r) * HH + col] = acc[r] * SCALE;
    }
    // ---- K (+apK) ----
    {
        const float4* W4 = reinterpret_cast<const float4*>(Kw) + col * 32;
        const float b = Kb[col];
        #pragma unroll
        for (int r = 0; r < 8; r++) acc[r] = b;
        #pragma unroll 8
        for (int j = 0; j < 32; j++) {
            const float4 w = W4[j];
            #pragma unroll
            for (int r = 0; r < 8; r++) {
                const float4 x = xk[r * 32 + j];
                acc[r] += w.x * x.x + w.y * x.y + w.z * x.z + w.w * x.w;
            }
        }
        #pragma unroll
        for (int r = 0; r < 8; r++)
            g_K[(row0 + r) * HH + col] = acc[r] + apK[(row0 + r) * HH + col];
    }
    // ---- V (+apV) ----
    {
        const float4* W4 = reinterpret_cast<const float4*>(Vw) + col * 32;
        const float b = Vb[col];
        #pragma unroll
        for (int r = 0; r < 8; r++) acc[r] = b;
        #pragma unroll 8
        for (int j = 0; j < 32; j++) {
            const float4 w = W4[j];
            #pragma unroll
            for (int r = 0; r < 8; r++) {
                const float4 x = xk[r * 32 + j];
                acc[r] += w.x * x.x + w.y * x.y + w.z * x.z + w.w * x.w;
            }
        }
        #pragma unroll
        for (int r = 0; r < 8; r++)
            g_V[(row0 + r) * HH + col] = acc[r] + apV[(row0 + r) * HH + col];
    }
}

__device__ __forceinline__ float dot4(float4 q, float4 a, float4 b) {
    return q.x * (a.x + b.x) + q.y * (a.y + b.y)
         + q.z * (a.z + b.z) + q.w * (a.w + b.w);
}
__device__ __forceinline__ float red8(float s) {
    s += __shfl_down_sync(0xffffffffu, s, 4);
    s += __shfl_down_sync(0xffffffffu, s, 2);
    s += __shfl_down_sync(0xffffffffu, s, 1);
    return s;
}

// ---------------------------------------------------------------------------
// Attention: one CTA per (b,l). 256 threads = 8 warps. m-loop unrolled x4
// for deep MLP (8 independent float4 loads in flight per thread).
// ---------------------------------------------------------------------------
__global__ __launch_bounds__(256) void attn_kernel(
    const float* __restrict__ tK, const float* __restrict__ tV,
    const int*   __restrict__ tmask, float* __restrict__ out)
{
    const int l = LL - 1 - blockIdx.x;   // heaviest rows first
    const int b = blockIdx.y;
    const int tid  = threadIdx.x;
    const int w    = tid >> 5;
    const int lane = tid & 31;

    __shared__ float4 sQ[32];
    __shared__ float  sP[NHH * LL];
    __shared__ float4 sRed[8 * 32];

    const bool masked = (tmask[b * LL + l] != 0);

    if (tid < 32)
        sQ[tid] = reinterpret_cast<const float4*>(g_Q)[(b * LL + l) * 32 + tid];
    __syncthreads();

    // ---------------- Phase A: logits ----------------
    if (!masked) {
        const float4* tK4 = reinterpret_cast<const float4*>(tK) + (size_t)(b * LL + l) * LL * 32 + lane;
        const float4* K4  = reinterpret_cast<const float4*>(g_K) + (size_t)b * LL * 32 + lane;
        const float4 q = sQ[lane];
        const int head = lane >> 3;
        const bool wr = ((lane & 7) == 0);
        int m = w;
        for (; m + 24 <= l; m += 32) {
            const float4 t0 = __ldcs(tK4 + (size_t)(m)      * 32);
            const float4 t1 = __ldcs(tK4 + (size_t)(m + 8)  * 32);
            const float4 t2 = __ldcs(tK4 + (size_t)(m + 16) * 32);
            const float4 t3 = __ldcs(tK4 + (size_t)(m + 24) * 32);
            const float4 k0 = K4[(m)      * 32];
            const float4 k1 = K4[(m + 8)  * 32];
            const float4 k2 = K4[(m + 16) * 32];
            const float4 k3 = K4[(m + 24) * 32];
            float s0 = red8(dot4(q, t0, k0));
            float s1 = red8(dot4(q, t1, k1));
            float s2 = red8(dot4(q, t2, k2));
            float s3 = red8(dot4(q, t3, k3));
            if (wr) {
                sP[head * LL + m]      = s0;
                sP[head * LL + m + 8]  = s1;
                sP[head * LL + m + 16] = s2;
                sP[head * LL + m + 24] = s3;
            }
        }
        for (; m <= l; m += 8) {
            const float4 t = __ldcs(tK4 + (size_t)m * 32);
            const float4 k = K4[m * 32];
            const float s = red8(dot4(q, t, k));
            if (wr) sP[head * LL + m] = s;
        }
    }
    __syncthreads();

    // ---------------- Phase B: softmax ----------------
    if (masked) {
        const float invL = 1.0f / (float)LL;
        for (int i = tid; i < NHH * LL; i += 256) sP[i] = invL;
    } else if (w < NHH) {
        const int h = w;
        float mx = -3.4e38f;
        for (int m = lane; m <= l; m += 32) mx = fmaxf(mx, sP[h * LL + m]);
        #pragma unroll
        for (int off = 16; off; off >>= 1)
            mx = fmaxf(mx, __shfl_xor_sync(0xffffffffu, mx, off));
        float sum = 0.0f;
        for (int m = lane; m <= l; m += 32) {
            const float e = __expf(sP[h * LL + m] - mx);
            sP[h * LL + m] = e;
            sum += e;
        }
        #pragma unroll
        for (int off = 16; off; off >>= 1)
            sum += __shfl_xor_sync(0xffffffffu, sum, off);
        const float inv = 1.0f / sum;
        for (int m = lane; m <= l; m += 32) sP[h * LL + m] *= inv;
    }
    __syncthreads();

    // ---------------- Phase C: output ----------------
    {
        const int mEnd = masked ? (LL - 1) : l;
        const float4* tV4 = reinterpret_cast<const float4*>(tV) + (size_t)(b * LL + l) * LL * 32 + lane;
        const float4* V4  = reinterpret_cast<const float4*>(g_V) + (size_t)b * LL * 32 + lane;
        const int head = lane >> 3;
        float4 acc = make_float4(0.f, 0.f, 0.f, 0.f);
        int m = w;
        for (; m + 24 <= mEnd; m += 32) {
            const float p0 = sP[head * LL + m];
            const float p1 = sP[head * LL + m + 8];
            const float p2 = sP[head * LL + m + 16];
            const float p3 = sP[head * LL + m + 24];
            const float4 t0 = __ldcs(tV4 + (size_t)(m)      * 32);
            const float4 t1 = __ldcs(tV4 + (size_t)(m + 8)  * 32);
            const float4 t2 = __ldcs(tV4 + (size_t)(m + 16) * 32);
            const float4 t3 = __ldcs(tV4 + (size_t)(m + 24) * 32);
            const float4 v0 = V4[(m)      * 32];
            const float4 v1 = V4[(m + 8)  * 32];
            const float4 v2 = V4[(m + 16) * 32];
            const float4 v3 = V4[(m + 24) * 32];
            acc.x += p0 * (t0.x + v0.x) + p1 * (t1.x + v1.x)
                   + p2 * (t2.x + v2.x) + p3 * (t3.x + v3.x);
            acc.y += p0 * (t0.y + v0.y) + p1 * (t1.y + v1.y)
                   + p2 * (t2.y + v2.y) + p3 * (t3.y + v3.y);
            acc.z += p0 * (t0.z + v0.z) + p1 * (t1.z + v1.z)
                   + p2 * (t2.z + v2.z) + p3 * (t3.z + v3.z);
            acc.w += p0 * (t0.w + v0.w) + p1 * (t1.w + v1.w)
                   + p2 * (t2.w + v2.w) + p3 * (t3.w + v3.w);
        }
        for (; m <= mEnd; m += 8) {
            const float p = sP[head * LL + m];
            const float4 t = __ldcs(tV4 + (size_t)m * 32);
            const float4 v = V4[m * 32];
            acc.x += p * (t.x + v.x);
            acc.y += p * (t.y + v.y);
            acc.z += p * (t.z + v.z);
            acc.w += p * (t.w + v.w);
        }
        sRed[w * 32 + lane] = acc;
    }
    __syncthreads();

    if (tid < 32) {
        float4 r = sRed[tid];
        #pragma unroll
        for (int w2 = 1; w2 < 8; w2++) {
            const float4 a = sRed[w2 * 32 + tid];
            r.x += a.x; r.y += a.y; r.z += a.z; r.w += a.w;
        }
        reinterpret_cast<float4*>(out)[(b * LL + l) * 32 + tid] = r;
    }
}

extern "C" void kernel_launch(void* const* d_in, const int* in_sizes, int n_in,
                              void* d_out, int out_size)
{
    const float* queries = (const float*)d_in[0];
    const float* keys    = (const float*)d_in[1];
    const int*   tmask   = (const int*)  d_in[2];
    // d_in[3] = attn_mask (causal triu, analytic -> unused)
    const float* tK      = (const float*)d_in[4];
    const float* tV      = (const float*)d_in[5];
    const float* apK     = (const float*)d_in[6];
    const float* apV     = (const float*)d_in[7];
    const float* Qw      = (const float*)d_in[8];
    const float* Qb      = (const float*)d_in[9];
    const float* Kw      = (const float*)d_in[10];
    const float* Kb      = (const float*)d_in[11];
    const float* Vw      = (const float*)d_in[12];
    const float* Vb      = (const float*)d_in[13];
    float* out = (float*)d_out;

    proj_kernel<<<200, 128>>>(queries, keys, apK, apV, Qw, Qb, Kw, Kb, Vw, Vb);
    dim3 grid(LL, BB);
    attn_kernel<<<grid, 256>>>(tK, tV, tmask, out);
}

// round 3
// speedup vs baseline: 1.4276x; 1.1972x over previous
#include <cuda_runtime.h>
#include <cuda_bf16.h>

#define BB 8
#define LL 200
#define HH 128
#define NHH 4
#define DHH 32
#define SCALE 0.17677669529663688f   // 1/sqrt(32)

__device__ float g_Q[BB * LL * HH];
__device__ float g_K[BB * LL * HH];
__device__ float g_V[BB * LL * HH];

// ---------------------------------------------------------------------------
// Projection: 200 CTAs x 8 rows, 128 threads (one output column each).
// Coalesced, double-buffered smem staging of W chunks (128 cols x 32 k).
// ---------------------------------------------------------------------------
__global__ __launch_bounds__(128) void proj_kernel(
    const float* __restrict__ queries, const float* __restrict__ keys,
    const float* __restrict__ apK, const float* __restrict__ apV,
    const float* __restrict__ Qw, const float* __restrict__ Qb,
    const float* __restrict__ Kw, const float* __restrict__ Kb,
    const float* __restrict__ Vw, const float* __restrict__ Vb)
{
    __shared__ float sxq[8 * 128];
    __shared__ float sxk[8 * 128];
    __shared__ float sW[2][128 * 33];   // padded: conflict-free column reads

    const int tid  = threadIdx.x;
    const int row0 = blockIdx.x * 8;    // 200 CTAs * 8 rows
    const int col  = tid;
    const int cgrp = tid >> 3;          // 0..15
    const int wrow = tid & 7;           // 0..7

    {
        const float4* q4 = reinterpret_cast<const float4*>(queries) + row0 * 32;
        const float4* k4 = reinterpret_cast<const float4*>(keys)    + row0 * 32;
        for (int idx = tid; idx < 256; idx += 128) {
            reinterpret_cast<float4*>(sxq)[idx] = q4[idx];
            reinterpret_cast<float4*>(sxk)[idx] = k4[idx];
        }
    }
    __syncthreads();

    const float* Wptr[3] = { Qw, Kw, Vw };
    const float* Bptr[3] = { Qb, Kb, Vb };

    for (int g = 0; g < 3; g++) {
        const float4* W4  = reinterpret_cast<const float4*>(Wptr[g]);
        const float4* xs4 = reinterpret_cast<const float4*>(g == 0 ? sxq : sxk);
        float acc[8];
        const float bias = Bptr[g][col];
        #pragma unroll
        for (int r = 0; r < 8; r++) acc[r] = bias;

        // prefetch chunk 0 (coalesced: 8 consecutive float4 per col-row = 1 line)
        float4 pre[8];
        #pragma unroll
        for (int ii = 0; ii < 8; ii++)
            pre[ii] = W4[(cgrp + 16 * ii) * 32 + wrow];

        int buf = 0;
        for (int kc = 0; kc < 4; kc++) {
            // commit prefetched chunk to smem
            #pragma unroll
            for (int ii = 0; ii < 8; ii++) {
                float* d = &sW[buf][(cgrp + 16 * ii) * 33 + wrow * 4];
                d[0] = pre[ii].x; d[1] = pre[ii].y; d[2] = pre[ii].z; d[3] = pre[ii].w;
            }
            __syncthreads();
            // prefetch next chunk while computing this one
            if (kc < 3) {
                #pragma unroll
                for (int ii = 0; ii < 8; ii++)
                    pre[ii] = W4[(cgrp + 16 * ii) * 32 + (kc + 1) * 8 + wrow];
            }
            const float* wp = &sW[buf][col * 33];
            #pragma unroll
            for (int i = 0; i < 8; i++) {
                const float w0 = wp[4 * i + 0];
                const float w1 = wp[4 * i + 1];
                const float w2 = wp[4 * i + 2];
                const float w3 = wp[4 * i + 3];
                #pragma unroll
                for (int r = 0; r < 8; r++) {
                    const float4 x = xs4[r * 32 + kc * 8 + i];
                    acc[r] += x.x * w0 + x.y * w1 + x.z * w2 + x.w * w3;
                }
            }
            buf ^= 1;
        }

        if (g == 0) {
            #pragma unroll
            for (int r = 0; r < 8; r++)
                g_Q[(row0 + r) * HH + col] = acc[r] * SCALE;
        } else if (g == 1) {
            #pragma unroll
            for (int r = 0; r < 8; r++)
                g_K[(row0 + r) * HH + col] = acc[r] + apK[(row0 + r) * HH + col];
        } else {
            #pragma unroll
            for (int r = 0; r < 8; r++)
                g_V[(row0 + r) * HH + col] = acc[r] + apV[(row0 + r) * HH + col];
        }
    }
}

__device__ __forceinline__ float dot4(float4 q, float4 a, float4 b) {
    return q.x * (a.x + b.x) + q.y * (a.y + b.y)
         + q.z * (a.z + b.z) + q.w * (a.w + b.w);
}
__device__ __forceinline__ float red8(float s) {
    s += __shfl_down_sync(0xffffffffu, s, 4);
    s += __shfl_down_sync(0xffffffffu, s, 2);
    s += __shfl_down_sync(0xffffffffu, s, 1);
    return s;
}

// ---------------------------------------------------------------------------
// Attention: one CTA per (b,l). 256 threads = 8 warps, x4 m-unroll,
// min 5 CTAs/SM for 40-warp occupancy.
// ---------------------------------------------------------------------------
__global__ __launch_bounds__(256, 5) void attn_kernel(
    const float* __restrict__ tK, const float* __restrict__ tV,
    const int*   __restrict__ tmask, float* __restrict__ out)
{
    const int l = LL - 1 - blockIdx.x;   // heaviest rows first
    const int b = blockIdx.y;
    const int tid  = threadIdx.x;
    const int w    = tid >> 5;
    const int lane = tid & 31;

    __shared__ float4 sQ[32];
    __shared__ float  sP[NHH * LL];
    __shared__ float4 sRed[8 * 32];

    const bool masked = (tmask[b * LL + l] != 0);

    if (tid < 32)
        sQ[tid] = reinterpret_cast<const float4*>(g_Q)[(b * LL + l) * 32 + tid];
    __syncthreads();

    // ---------------- Phase A: logits ----------------
    if (!masked) {
        const float4* tK4 = reinterpret_cast<const float4*>(tK) + (size_t)(b * LL + l) * LL * 32 + lane;
        const float4* K4  = reinterpret_cast<const float4*>(g_K) + (size_t)b * LL * 32 + lane;
        const float4 q = sQ[lane];
        const int head = lane >> 3;
        const bool wr = ((lane & 7) == 0);
        int m = w;
        for (; m + 24 <= l; m += 32) {
            const float4 t0 = __ldcs(tK4 + (size_t)(m)      * 32);
            const float4 t1 = __ldcs(tK4 + (size_t)(m + 8)  * 32);
            const float4 t2 = __ldcs(tK4 + (size_t)(m + 16) * 32);
            const float4 t3 = __ldcs(tK4 + (size_t)(m + 24) * 32);
            const float4 k0 = K4[(m)      * 32];
            const float4 k1 = K4[(m + 8)  * 32];
            const float4 k2 = K4[(m + 16) * 32];
            const float4 k3 = K4[(m + 24) * 32];
            float s0 = red8(dot4(q, t0, k0));
            float s1 = red8(dot4(q, t1, k1));
            float s2 = red8(dot4(q, t2, k2));
            float s3 = red8(dot4(q, t3, k3));
            if (wr) {
                sP[head * LL + m]      = s0;
                sP[head * LL + m + 8]  = s1;
                sP[head * LL + m + 16] = s2;
                sP[head * LL + m + 24] = s3;
            }
        }
        for (; m <= l; m += 8) {
            const float4 t = __ldcs(tK4 + (size_t)m * 32);
            const float4 k = K4[m * 32];
            const float s = red8(dot4(q, t, k));
            if (wr) sP[head * LL + m] = s;
        }
    }
    __syncthreads();

    // ---------------- Phase B: softmax ----------------
    if (masked) {
        const float invL = 1.0f / (float)LL;
        for (int i = tid; i < NHH * LL; i += 256) sP[i] = invL;
    } else if (w < NHH) {
        const int h = w;
        float mx = -3.4e38f;
        for (int m = lane; m <= l; m += 32) mx = fmaxf(mx, sP[h * LL + m]);
        #pragma unroll
        for (int off = 16; off; off >>= 1)
            mx = fmaxf(mx, __shfl_xor_sync(0xffffffffu, mx, off));
        float sum = 0.0f;
        for (int m = lane; m <= l; m += 32) {
            const float e = __expf(sP[h * LL + m] - mx);
            sP[h * LL + m] = e;
            sum += e;
        }
        #pragma unroll
        for (int off = 16; off; off >>= 1)
            sum += __shfl_xor_sync(0xffffffffu, sum, off);
        const float inv = 1.0f / sum;
        for (int m = lane; m <= l; m += 32) sP[h * LL + m] *= inv;
    }
    __syncthreads();

    // ---------------- Phase C: output ----------------
    {
        const int mEnd = masked ? (LL - 1) : l;
        const float4* tV4 = reinterpret_cast<const float4*>(tV) + (size_t)(b * LL + l) * LL * 32 + lane;
        const float4* V4  = reinterpret_cast<const float4*>(g_V) + (size_t)b * LL * 32 + lane;
        const int head = lane >> 3;
        float4 acc = make_float4(0.f, 0.f, 0.f, 0.f);
        int m = w;
        for (; m + 24 <= mEnd; m += 32) {
            const float p0 = sP[head * LL + m];
            const float p1 = sP[head * LL + m + 8];
            const float p2 = sP[head * LL + m + 16];
            const float p3 = sP[head * LL + m + 24];
            const float4 t0 = __ldcs(tV4 + (size_t)(m)      * 32);
            const float4 t1 = __ldcs(tV4 + (size_t)(m + 8)  * 32);
            const float4 t2 = __ldcs(tV4 + (size_t)(m + 16) * 32);
            const float4 t3 = __ldcs(tV4 + (size_t)(m + 24) * 32);
            const float4 v0 = V4[(m)      * 32];
            const float4 v1 = V4[(m + 8)  * 32];
            const float4 v2 = V4[(m + 16) * 32];
            const float4 v3 = V4[(m + 24) * 32];
            acc.x += p0 * (t0.x + v0.x) + p1 * (t1.x + v1.x)
                   + p2 * (t2.x + v2.x) + p3 * (t3.x + v3.x);
            acc.y += p0 * (t0.y + v0.y) + p1 * (t1.y + v1.y)
                   + p2 * (t2.y + v2.y) + p3 * (t3.y + v3.y);
            acc.z += p0 * (t0.z + v0.z) + p1 * (t1.z + v1.z)
                   + p2 * (t2.z + v2.z) + p3 * (t3.z + v3.z);
            acc.w += p0 * (t0.w + v0.w) + p1 * (t1.w + v1.w)
                   + p2 * (t2.w + v2.w) + p3 * (t3.w + v3.w);
        }
        for (; m <= mEnd; m += 8) {
            const float p = sP[head * LL + m];
            const float4 t = __ldcs(tV4 + (size_t)m * 32);
            const float4 v = V4[m * 32];
            acc.x += p * (t.x + v.x);
            acc.y += p * (t.y + v.y);
            acc.z += p * (t.z + v.z);
            acc.w += p * (t.w + v.w);
        }
        sRed[w * 32 + lane] = acc;
    }
    __syncthreads();

    if (tid < 32) {
        float4 r = sRed[tid];
        #pragma unroll
        for (int w2 = 1; w2 < 8; w2++) {
            const float4 a = sRed[w2 * 32 + tid];
            r.x += a.x; r.y += a.y; r.z += a.z; r.w += a.w;
        }
        reinterpret_cast<float4*>(out)[(b * LL + l) * 32 + tid] = r;
    }
}

extern "C" void kernel_launch(void* const* d_in, const int* in_sizes, int n_in,
                              void* d_out, int out_size)
{
    const float* queries = (const float*)d_in[0];
    const float* keys    = (const float*)d_in[1];
    const int*   tmask   = (const int*)  d_in[2];
    // d_in[3] = attn_mask (causal triu, analytic -> unused)
    const float* tK      = (const float*)d_in[4];
    const float* tV      = (const float*)d_in[5];
    const float* apK     = (const float*)d_in[6];
    const float* apV     = (const float*)d_in[7];
    const float* Qw      = (const float*)d_in[8];
    const float* Qb      = (const float*)d_in[9];
    const float* Kw      = (const float*)d_in[10];
    const float* Kb      = (const float*)d_in[11];
    const float* Vw      = (const float*)d_in[12];
    const float* Vb      = (const float*)d_in[13];
    float* out = (float*)d_out;

    proj_kernel<<<200, 128>>>(queries, keys, apK, apV, Qw, Qb, Kw, Kb, Vw, Vb);
    dim3 grid(LL, BB);
    attn_kernel<<<grid, 256>>>(tK, tV, tmask, out);
}